// round 10
// baseline (speedup 1.0000x reference)
#include <cuda_runtime.h>
#include <cuda_fp16.h>
#include <math.h>
#include <stdint.h>

#define BB 2
#define SS 4096
#define DD 512
#define HH 8
#define HD 64
#define MROWS (BB*SS)   // 8192

typedef unsigned long long u64;
typedef unsigned int u32;

// ------------------------- device scratch ----------------------------------
__device__ float g_q[MROWS * DD];
__device__ float g_k[MROWS * DD];
__device__ float g_v[MROWS * DD];
__device__ float g_att[MROWS * DD];
__device__ __half g_qh[MROWS * DD];    // fp16(q * 0.125), post-rope
__device__ __half g_kh[MROWS * DD];    // fp16 hi of k, post-rope
__device__ __half g_kl[MROWS * DD];    // fp16 lo of k
__device__ __half g_vth[MROWS * DD];   // V^T [bh][d][s] fp16 hi
__device__ __half g_vtl[MROWS * DD];   // V^T fp16 lo

// ---------------- f32x2 packed-math helpers (GEMM) --------------------------
__device__ __forceinline__ u64 ffma2(u64 a, u64 b, u64 c) {
    u64 d; asm("fma.rn.f32x2 %0, %1, %2, %3;" : "=l"(d) : "l"(a), "l"(b), "l"(c)); return d;
}
__device__ __forceinline__ u64 pack2(float lo, float hi) {
    u64 r; asm("mov.b64 %0, {%1, %2};" : "=l"(r) : "f"(lo), "f"(hi)); return r;
}
__device__ __forceinline__ void lds_v2b64(u64 &a, u64 &b, unsigned addr) {
    asm volatile("ld.shared.v2.b64 {%0, %1}, [%2];" : "=l"(a), "=l"(b) : "r"(addr));
}
__device__ __forceinline__ u32 pkh(float a, float b) {
    __half2 t = __floats2half2_rn(a, b);   // x=a (low), y=b (high)
    return *(u32*)&t;
}
__device__ __forceinline__ float h2f(float f) {       // fp16 round-trip
    return __half2float(__float2half_rn(f));
}

// ---------------- mma.sync fp16 (baseline PTX, works on sm_103) -------------
__device__ __forceinline__ void mma16816h(float* c, const u32* a, u32 b0, u32 b1) {
    asm("mma.sync.aligned.m16n8k16.row.col.f32.f16.f16.f32 "
        "{%0,%1,%2,%3}, {%4,%5,%6,%7}, {%8,%9}, {%0,%1,%2,%3};"
        : "+f"(c[0]), "+f"(c[1]), "+f"(c[2]), "+f"(c[3])
        : "r"(a[0]), "r"(a[1]), "r"(a[2]), "r"(a[3]), "r"(b0), "r"(b1));
}

// ---------------------------------------------------------------------------
// C[M x 512] = A[M x 512] * W[512 x 512]^T  (FFMA2 SIMT gemm — R7 proven)
// ---------------------------------------------------------------------------
__global__ __launch_bounds__(256) void gemm_nt(const float* __restrict__ A,
                                               const float* __restrict__ W,
                                               float* __restrict__ C) {
    __shared__ float As[16][132];
    __shared__ float Ws[16][132];

    const int bm = blockIdx.y * 128;
    const int bn = blockIdx.x * 128;
    const int t  = threadIdx.x;
    const int tm = (t >> 4) * 8;
    const int tn = (t & 15) * 8;

    u64 acc2[8][4];
#pragma unroll
    for (int i = 0; i < 8; i++)
#pragma unroll
        for (int j = 0; j < 4; j++) acc2[i][j] = 0ull;

    const unsigned sW = (unsigned)__cvta_generic_to_shared(&Ws[0][0]);

    for (int k0 = 0; k0 < 512; k0 += 16) {
#pragma unroll
        for (int i = 0; i < 2; i++) {
            int idx = t + i * 256;
            int row = idx >> 2;
            int kc  = (idx & 3) << 2;
            float4 av = *(const float4*)(A + (size_t)(bm + row) * 512 + k0 + kc);
            As[kc + 0][row] = av.x; As[kc + 1][row] = av.y;
            As[kc + 2][row] = av.z; As[kc + 3][row] = av.w;
            float4 wv = *(const float4*)(W + (size_t)(bn + row) * 512 + k0 + kc);
            Ws[kc + 0][row] = wv.x; Ws[kc + 1][row] = wv.y;
            Ws[kc + 2][row] = wv.z; Ws[kc + 3][row] = wv.w;
        }
        __syncthreads();

#pragma unroll
        for (int k = 0; k < 16; k++) {
            float4 a0 = *(const float4*)&As[k][tm];
            float4 a1 = *(const float4*)&As[k][tm + 4];
            u64 b2[4];
            unsigned wb = sW + (unsigned)(k * 132 + tn) * 4u;
            lds_v2b64(b2[0], b2[1], wb);
            lds_v2b64(b2[2], b2[3], wb + 16u);
            float a[8] = {a0.x, a0.y, a0.z, a0.w, a1.x, a1.y, a1.z, a1.w};
#pragma unroll
            for (int i = 0; i < 8; i++) {
                u64 ai = pack2(a[i], a[i]);
#pragma unroll
                for (int j = 0; j < 4; j++)
                    acc2[i][j] = ffma2(ai, b2[j], acc2[i][j]);
            }
        }
        __syncthreads();
    }

#pragma unroll
    for (int i = 0; i < 8; i++) {
        union { u64 u[2]; float4 f; } o0, o1;
        o0.u[0] = acc2[i][0]; o0.u[1] = acc2[i][1];
        o1.u[0] = acc2[i][2]; o1.u[1] = acc2[i][3];
        float* crow = C + (size_t)(bm + tm + i) * 512 + bn + tn;
        *(float4*)crow       = o0.f;
        *(float4*)(crow + 4) = o1.f;
    }
}

// ---------------------------------------------------------------------------
// Fused axial RoPE + fp16 convert: q -> qh (scaled, single fp16);
// k -> kh + kl (fp16 split). One thread per (row, head, 4-dim chunk).
// ---------------------------------------------------------------------------
__global__ __launch_bounds__(256) void rope_h(const float* __restrict__ q,
                                              const float* __restrict__ k,
                                              __half* __restrict__ qh,
                                              __half* __restrict__ kh,
                                              __half* __restrict__ kl) {
    int idx = blockIdx.x * 256 + threadIdx.x;
    if (idx >= MROWS * HH * 16) return;
    int c   = idx & 15;
    int rh  = idx >> 4;
    int h   = rh & 7;
    int row = rh >> 3;
    int s   = row & (SS - 1);

    int d0 = c * 4;
    float pos; int jb;
    if (d0 < 32) { pos = (float)(s >> 5); jb = c * 2; }          // t-rope
    else         { pos = (float)(s & 31); jb = (c - 8) * 2; }    // v-rope

    const float L = 13.2877123795494f / 16.0f;
    float a0 = pos * exp2f(-(float)jb * L);
    float a1 = pos * exp2f(-(float)(jb + 1) * L);
    float s0, c0, s1, c1;
    sincosf(a0, &s0, &c0);
    sincosf(a1, &s1, &c1);

    size_t base = (size_t)row * 512 + h * 64 + d0;
    int ui = (int)(base >> 2);   // uint2 index into half buffers

    // q (scaled) — single fp16
    {
        float4 x = *(const float4*)(q + base);
        float e0 = (x.x * c0 - x.y * s0) * 0.125f;
        float o0 = (x.x * s0 + x.y * c0) * 0.125f;
        float e1 = (x.z * c1 - x.w * s1) * 0.125f;
        float o1 = (x.z * s1 + x.w * c1) * 0.125f;
        ((uint2*)qh)[ui] = make_uint2(pkh(e0, o0), pkh(e1, o1));
    }
    // k — fp16 hi/lo split
    {
        float4 x = *(const float4*)(k + base);
        float f[4];
        f[0] = x.x * c0 - x.y * s0;
        f[1] = x.x * s0 + x.y * c0;
        f[2] = x.z * c1 - x.w * s1;
        f[3] = x.z * s1 + x.w * c1;
        float hh[4];
#pragma unroll
        for (int e = 0; e < 4; e++) hh[e] = h2f(f[e]);
        ((uint2*)kh)[ui] = make_uint2(pkh(hh[0], hh[1]), pkh(hh[2], hh[3]));
        ((uint2*)kl)[ui] = make_uint2(pkh(f[0] - hh[0], f[1] - hh[1]),
                                      pkh(f[2] - hh[2], f[3] - hh[3]));
    }
}

// ---------------------------------------------------------------------------
// Transpose + fp16 split V: v[b,s,h,d] -> vt[bh][d][s].
// ---------------------------------------------------------------------------
__global__ __launch_bounds__(256) void v_split_t(const float* __restrict__ v,
                                                 __half* __restrict__ vth,
                                                 __half* __restrict__ vtl) {
    __shared__ float tile[64][65];
    const int bh = blockIdx.y;
    const int b  = bh >> 3;
    const int h  = bh & 7;
    const int s0 = blockIdx.x * 64;
    const int t  = threadIdx.x;

#pragma unroll
    for (int i = 0; i < 16; i++) {
        int idx = t + i * 256;
        int sl = idx >> 6, d = idx & 63;
        tile[sl][d] = v[((size_t)(b * SS) + s0 + sl) * DD + h * HD + d];
    }
    __syncthreads();

#pragma unroll
    for (int i = 0; i < 8; i++) {
        int j = t + i * 256;
        int d = j >> 5, sp = j & 31;
        float f0 = tile[sp * 2][d], f1 = tile[sp * 2 + 1][d];
        float hi0 = h2f(f0), hi1 = h2f(f1);
        size_t o = ((((size_t)bh * HD + d) * SS + s0) >> 1) + sp;
        ((u32*)vth)[o] = pkh(hi0, hi1);
        ((u32*)vtl)[o] = pkh(f0 - hi0, f1 - hi1);
    }
}

// ---------------------------------------------------------------------------
// Flash attention, fp16 HMMA, 4 products per tile (2 QK + 2 PV).
// p' = exp2(s*log2e - 8): exact power-of-2 scale, cancels in O = sum p'v / sum p'.
// Fragment layout identical to R7 (validated); only dtype + product count differ.
// ---------------------------------------------------------------------------
#define PADR 36

__global__ __launch_bounds__(256) void attn_mma(
    const __half* __restrict__ qh_, const __half* __restrict__ kh_,
    const __half* __restrict__ kl_,
    const __half* __restrict__ vth_, const __half* __restrict__ vtl_,
    float* __restrict__ out) {
    __shared__ u32 ksh_h[64 * PADR], ksh_l[64 * PADR];
    __shared__ u32 vsh_h[64 * PADR], vsh_l[64 * PADR];

    const int tid = threadIdx.x;
    const int w = tid >> 5, lane = tid & 31;
    const int g = lane >> 2, t = lane & 3;
    const int bh = blockIdx.y, b = bh >> 3, h = bh & 7;
    const int q0 = blockIdx.x * 128 + w * 16;

    const u32* qh32 = (const u32*)qh_;
    const u32* kh32 = (const u32*)kh_;
    const u32* kl32 = (const u32*)kl_;
    const u32* vth32 = (const u32*)vth_;
    const u32* vtl32 = (const u32*)vtl_;

    u32 aQ[4][4];
    {
        const size_t rg  = (size_t)(b * SS + q0 + g) * 256 + h * 32;
        const size_t rg8 = rg + 8 * 256;
#pragma unroll
        for (int kb = 0; kb < 4; kb++) {
            aQ[kb][0] = qh32[rg  + kb * 8 + t];
            aQ[kb][1] = qh32[rg8 + kb * 8 + t];
            aQ[kb][2] = qh32[rg  + kb * 8 + 4 + t];
            aQ[kb][3] = qh32[rg8 + kb * 8 + 4 + t];
        }
    }

    float oacc[8][4];
#pragma unroll
    for (int j = 0; j < 8; j++)
#pragma unroll
        for (int e = 0; e < 4; e++) oacc[j][e] = 0.0f;
    float lsum0 = 0.0f, lsum1 = 0.0f;

    for (int kt = 0; kt < SS; kt += 64) {
        __syncthreads();
        {
            const size_t kg = (size_t)(b * SS + kt) * 256 + h * 32;
            const size_t vg = (size_t)bh * 64 * 2048 + (kt >> 1);
#pragma unroll
            for (int i = 0; i < 2; i++) {
                int idx = tid + i * 256;
                int s = idx >> 3, c = idx & 7;
                int so = s * PADR + c * 4;
                uint4 a = *(const uint4*)(kh32 + kg + (size_t)s * 256 + c * 4);
                ksh_h[so] = a.x; ksh_h[so + 1] = a.y; ksh_h[so + 2] = a.z; ksh_h[so + 3] = a.w;
                uint4 bq = *(const uint4*)(kl32 + kg + (size_t)s * 256 + c * 4);
                ksh_l[so] = bq.x; ksh_l[so + 1] = bq.y; ksh_l[so + 2] = bq.z; ksh_l[so + 3] = bq.w;
                uint4 cq = *(const uint4*)(vth32 + vg + (size_t)s * 2048 + c * 4);
                vsh_h[so] = cq.x; vsh_h[so + 1] = cq.y; vsh_h[so + 2] = cq.z; vsh_h[so + 3] = cq.w;
                uint4 dq = *(const uint4*)(vtl32 + vg + (size_t)s * 2048 + c * 4);
                vsh_l[so] = dq.x; vsh_l[so + 1] = dq.y; vsh_l[so + 2] = dq.z; vsh_l[so + 3] = dq.w;
            }
        }
        __syncthreads();

        float sacc[8][4];
#pragma unroll
        for (int j = 0; j < 8; j++)
#pragma unroll
            for (int e = 0; e < 4; e++) sacc[j][e] = 0.0f;

#pragma unroll
        for (int kb = 0; kb < 4; kb++) {
#pragma unroll
            for (int j = 0; j < 8; j++) {
                int base = (j * 8 + g) * PADR + kb * 8 + t;
                u32 bh0 = ksh_h[base], bh1 = ksh_h[base + 4];
                u32 bl0 = ksh_l[base], bl1 = ksh_l[base + 4];
                mma16816h(sacc[j], aQ[kb], bh0, bh1);
                mma16816h(sacc[j], aQ[kb], bl0, bl1);
            }
        }

        // p' = exp2(s*log2e - 8)  (scale cancels in the final ratio)
        const float L2E = 1.44269504f;
        u32 aP[4][4];
#pragma unroll
        for (int j = 0; j < 8; j++) {
            float p0 = exp2f(sacc[j][0] * L2E - 8.0f);
            float p1 = exp2f(sacc[j][1] * L2E - 8.0f);
            float p2 = exp2f(sacc[j][2] * L2E - 8.0f);
            float p3 = exp2f(sacc[j][3] * L2E - 8.0f);
            lsum0 += p0 + p1;
            lsum1 += p2 + p3;
            int kbp = j >> 1, r0 = (j & 1) * 2;
            aP[kbp][r0]     = pkh(p0, p1);
            aP[kbp][r0 + 1] = pkh(p2, p3);
        }

#pragma unroll
        for (int kbp = 0; kbp < 4; kbp++) {
#pragma unroll
            for (int j = 0; j < 8; j++) {
                int base = (j * 8 + g) * PADR + kbp * 8 + t;
                u32 vh0 = vsh_h[base], vh1 = vsh_h[base + 4];
                u32 vl0 = vsh_l[base], vl1 = vsh_l[base + 4];
                mma16816h(oacc[j], aP[kbp], vh0, vh1);
                mma16816h(oacc[j], aP[kbp], vl0, vl1);
            }
        }
    }

    lsum0 += __shfl_xor_sync(0xFFFFFFFFu, lsum0, 1);
    lsum0 += __shfl_xor_sync(0xFFFFFFFFu, lsum0, 2);
    lsum1 += __shfl_xor_sync(0xFFFFFFFFu, lsum1, 1);
    lsum1 += __shfl_xor_sync(0xFFFFFFFFu, lsum1, 2);
    float inv0 = 1.0f / lsum0, inv1 = 1.0f / lsum1;

    float* o0 = out + (size_t)(b * SS + q0 + g) * 512 + h * 64;
    float* o1 = o0 + 8 * 512;
#pragma unroll
    for (int j = 0; j < 8; j++) {
        *(float2*)(o0 + j * 8 + 2 * t) = make_float2(oacc[j][0] * inv0, oacc[j][1] * inv0);
        *(float2*)(o1 + j * 8 + 2 * t) = make_float2(oacc[j][2] * inv1, oacc[j][3] * inv1);
    }
}

// ---------------------------------------------------------------------------
extern "C" void kernel_launch(void* const* d_in, const int* in_sizes, int n_in,
                              void* d_out, int out_size) {
    const float* x  = (const float*)d_in[0];
    const float* Wq = (const float*)d_in[1];
    const float* Wk = (const float*)d_in[2];
    const float* Wv = (const float*)d_in[3];
    const float* Wo = (const float*)d_in[4];
    float* out = (float*)d_out;

    float *q, *k, *v, *att;
    __half *qh, *kh, *kl, *vth, *vtl;
    cudaGetSymbolAddress((void**)&q,   g_q);
    cudaGetSymbolAddress((void**)&k,   g_k);
    cudaGetSymbolAddress((void**)&v,   g_v);
    cudaGetSymbolAddress((void**)&att, g_att);
    cudaGetSymbolAddress((void**)&qh,  g_qh);
    cudaGetSymbolAddress((void**)&kh,  g_kh);
    cudaGetSymbolAddress((void**)&kl,  g_kl);
    cudaGetSymbolAddress((void**)&vth, g_vth);
    cudaGetSymbolAddress((void**)&vtl, g_vtl);

    dim3 ggrid(512 / 128, MROWS / 128);   // (4, 64)

    gemm_nt<<<ggrid, 256>>>(x, Wq, q);
    gemm_nt<<<ggrid, 256>>>(x, Wk, k);
    gemm_nt<<<ggrid, 256>>>(x, Wv, v);

    int nch = MROWS * HH * 16;
    rope_h<<<(nch + 255) / 256, 256>>>(q, k, qh, kh, kl);

    v_split_t<<<dim3(SS / 64, BB * HH), 256>>>(v, vth, vtl);

    attn_mma<<<dim3(SS / 128, BB * HH), 256>>>(qh, kh, kl, vth, vtl, att);

    gemm_nt<<<ggrid, 256>>>(att, Wo, out);
}

// round 12
// speedup vs baseline: 1.3138x; 1.3138x over previous
#include <cuda_runtime.h>
#include <cuda_bf16.h>
#include <math.h>
#include <stdint.h>

#define BB 2
#define SS 4096
#define DD 512
#define HH 8
#define HD 64
#define MROWS (BB*SS)   // 8192

typedef unsigned long long u64;
typedef unsigned int u32;

// ------------------------- device scratch ----------------------------------
__device__ float g_q[MROWS * DD];
__device__ float g_k[MROWS * DD];
__device__ float g_v[MROWS * DD];
__device__ float g_att[MROWS * DD];
__device__ __nv_bfloat16 g_qhi[MROWS * DD];
__device__ __nv_bfloat16 g_qlo[MROWS * DD];
__device__ __nv_bfloat16 g_khi[MROWS * DD];
__device__ __nv_bfloat16 g_klo[MROWS * DD];
__device__ __nv_bfloat16 g_vthi[MROWS * DD];   // layout [bh][d][s]
__device__ __nv_bfloat16 g_vtlo[MROWS * DD];

// ---------------- helpers ---------------------------------------------------
__device__ __forceinline__ u64 ffma2(u64 a, u64 b, u64 c) {
    u64 d; asm("fma.rn.f32x2 %0, %1, %2, %3;" : "=l"(d) : "l"(a), "l"(b), "l"(c)); return d;
}
__device__ __forceinline__ u64 pack2(float lo, float hi) {
    u64 r; asm("mov.b64 %0, {%1, %2};" : "=l"(r) : "f"(lo), "f"(hi)); return r;
}
__device__ __forceinline__ void lds_v2b64(u64 &a, u64 &b, unsigned addr) {
    asm volatile("ld.shared.v2.b64 {%0, %1}, [%2];" : "=l"(a), "=l"(b) : "r"(addr));
}
__device__ __forceinline__ u32 pkbf(float a, float b) {
    __nv_bfloat162 t = __floats2bfloat162_rn(a, b);
    return *(u32*)&t;
}
__device__ __forceinline__ u32 smem_u32p(const void* ptr) {
    u32 a;
    asm("{ .reg .u64 t; cvta.to.shared.u64 t, %1; cvt.u32.u64 %0, t; }" : "=r"(a) : "l"(ptr));
    return a;
}
__device__ __forceinline__ void cpasync16(u32 saddr, const void* g) {
    asm volatile("cp.async.cg.shared.global [%0], [%1], 16;" :: "r"(saddr), "l"(g) : "memory");
}
__device__ __forceinline__ void cp_commit() {
    asm volatile("cp.async.commit_group;" ::: "memory");
}
__device__ __forceinline__ void cp_wait0() {
    asm volatile("cp.async.wait_group 0;" ::: "memory");
}

// ---------------- mma.sync bf16 (baseline PTX, works on sm_103) -------------
__device__ __forceinline__ void mma16816(float* c, const u32* a, u32 b0, u32 b1) {
    asm("mma.sync.aligned.m16n8k16.row.col.f32.bf16.bf16.f32 "
        "{%0,%1,%2,%3}, {%4,%5,%6,%7}, {%8,%9}, {%0,%1,%2,%3};"
        : "+f"(c[0]), "+f"(c[1]), "+f"(c[2]), "+f"(c[3])
        : "r"(a[0]), "r"(a[1]), "r"(a[2]), "r"(a[3]), "r"(b0), "r"(b1));
}

// ---------------------------------------------------------------------------
// C[M x 512] = A[M x 512] * W[512 x 512]^T  (FFMA2 SIMT gemm — R7 proven)
// ---------------------------------------------------------------------------
__global__ __launch_bounds__(256) void gemm_nt(const float* __restrict__ A,
                                               const float* __restrict__ W,
                                               float* __restrict__ C) {
    __shared__ float As[16][132];
    __shared__ float Ws[16][132];

    const int bm = blockIdx.y * 128;
    const int bn = blockIdx.x * 128;
    const int t  = threadIdx.x;
    const int tm = (t >> 4) * 8;
    const int tn = (t & 15) * 8;

    u64 acc2[8][4];
#pragma unroll
    for (int i = 0; i < 8; i++)
#pragma unroll
        for (int j = 0; j < 4; j++) acc2[i][j] = 0ull;

    const unsigned sW = (unsigned)__cvta_generic_to_shared(&Ws[0][0]);

    for (int k0 = 0; k0 < 512; k0 += 16) {
#pragma unroll
        for (int i = 0; i < 2; i++) {
            int idx = t + i * 256;
            int row = idx >> 2;
            int kc  = (idx & 3) << 2;
            float4 av = *(const float4*)(A + (size_t)(bm + row) * 512 + k0 + kc);
            As[kc + 0][row] = av.x; As[kc + 1][row] = av.y;
            As[kc + 2][row] = av.z; As[kc + 3][row] = av.w;
            float4 wv = *(const float4*)(W + (size_t)(bn + row) * 512 + k0 + kc);
            Ws[kc + 0][row] = wv.x; Ws[kc + 1][row] = wv.y;
            Ws[kc + 2][row] = wv.z; Ws[kc + 3][row] = wv.w;
        }
        __syncthreads();

#pragma unroll
        for (int k = 0; k < 16; k++) {
            float4 a0 = *(const float4*)&As[k][tm];
            float4 a1 = *(const float4*)&As[k][tm + 4];
            u64 b2[4];
            unsigned wb = sW + (unsigned)(k * 132 + tn) * 4u;
            lds_v2b64(b2[0], b2[1], wb);
            lds_v2b64(b2[2], b2[3], wb + 16u);
            float a[8] = {a0.x, a0.y, a0.z, a0.w, a1.x, a1.y, a1.z, a1.w};
#pragma unroll
            for (int i = 0; i < 8; i++) {
                u64 ai = pack2(a[i], a[i]);
#pragma unroll
                for (int j = 0; j < 4; j++)
                    acc2[i][j] = ffma2(ai, b2[j], acc2[i][j]);
            }
        }
        __syncthreads();
    }

#pragma unroll
    for (int i = 0; i < 8; i++) {
        union { u64 u[2]; float4 f; } o0, o1;
        o0.u[0] = acc2[i][0]; o0.u[1] = acc2[i][1];
        o1.u[0] = acc2[i][2]; o1.u[1] = acc2[i][3];
        float* crow = C + (size_t)(bm + tm + i) * 512 + bn + tn;
        *(float4*)crow       = o0.f;
        *(float4*)(crow + 4) = o1.f;
    }
}

// ---------------------------------------------------------------------------
// Fused axial RoPE + bf16 split (R9-proven): q scaled by 0.125.
// ---------------------------------------------------------------------------
__global__ __launch_bounds__(256) void rope_split(const float* __restrict__ q,
                                                  const float* __restrict__ k,
                                                  __nv_bfloat16* __restrict__ qhi,
                                                  __nv_bfloat16* __restrict__ qlo,
                                                  __nv_bfloat16* __restrict__ khi,
                                                  __nv_bfloat16* __restrict__ klo) {
    int idx = blockIdx.x * 256 + threadIdx.x;
    if (idx >= MROWS * HH * 16) return;
    int c   = idx & 15;
    int rh  = idx >> 4;
    int h   = rh & 7;
    int row = rh >> 3;
    int s   = row & (SS - 1);

    int d0 = c * 4;
    float pos; int jb;
    if (d0 < 32) { pos = (float)(s >> 5); jb = c * 2; }
    else         { pos = (float)(s & 31); jb = (c - 8) * 2; }

    const float L = 13.2877123795494f / 16.0f;
    float a0 = pos * exp2f(-(float)jb * L);
    float a1 = pos * exp2f(-(float)(jb + 1) * L);
    float s0, c0, s1, c1;
    sincosf(a0, &s0, &c0);
    sincosf(a1, &s1, &c1);

    size_t base = (size_t)row * 512 + h * 64 + d0;
    int ui = (int)(base >> 2);

    {
        float4 x = *(const float4*)(q + base);
        float f[4];
        f[0] = (x.x * c0 - x.y * s0) * 0.125f;
        f[1] = (x.x * s0 + x.y * c0) * 0.125f;
        f[2] = (x.z * c1 - x.w * s1) * 0.125f;
        f[3] = (x.z * s1 + x.w * c1) * 0.125f;
        float hh[4];
#pragma unroll
        for (int e = 0; e < 4; e++) hh[e] = __bfloat162float(__float2bfloat16(f[e]));
        ((uint2*)qhi)[ui] = make_uint2(pkbf(hh[0], hh[1]), pkbf(hh[2], hh[3]));
        ((uint2*)qlo)[ui] = make_uint2(pkbf(f[0] - hh[0], f[1] - hh[1]),
                                       pkbf(f[2] - hh[2], f[3] - hh[3]));
    }
    {
        float4 x = *(const float4*)(k + base);
        float f[4];
        f[0] = x.x * c0 - x.y * s0;
        f[1] = x.x * s0 + x.y * c0;
        f[2] = x.z * c1 - x.w * s1;
        f[3] = x.z * s1 + x.w * c1;
        float hh[4];
#pragma unroll
        for (int e = 0; e < 4; e++) hh[e] = __bfloat162float(__float2bfloat16(f[e]));
        ((uint2*)khi)[ui] = make_uint2(pkbf(hh[0], hh[1]), pkbf(hh[2], hh[3]));
        ((uint2*)klo)[ui] = make_uint2(pkbf(f[0] - hh[0], f[1] - hh[1]),
                                       pkbf(f[2] - hh[2], f[3] - hh[3]));
    }
}

// ---------------------------------------------------------------------------
// Transpose + split V: v[b,s,h,d] -> vt[bh][d][s] in bf16 hi/lo (R9-proven).
// ---------------------------------------------------------------------------
__global__ __launch_bounds__(256) void v_split_t(const float* __restrict__ v,
                                                 __nv_bfloat16* __restrict__ vthi,
                                                 __nv_bfloat16* __restrict__ vtlo) {
    __shared__ float tile[64][65];
    const int bh = blockIdx.y;
    const int b  = bh >> 3;
    const int h  = bh & 7;
    const int s0 = blockIdx.x * 64;
    const int t  = threadIdx.x;

#pragma unroll
    for (int i = 0; i < 16; i++) {
        int idx = t + i * 256;
        int sl = idx >> 6, d = idx & 63;
        tile[sl][d] = v[((size_t)(b * SS) + s0 + sl) * DD + h * HD + d];
    }
    __syncthreads();

#pragma unroll
    for (int i = 0; i < 8; i++) {
        int j = t + i * 256;
        int d = j >> 5, sp = j & 31;
        float f0 = tile[sp * 2][d], f1 = tile[sp * 2 + 1][d];
        float hi0 = __bfloat162float(__float2bfloat16(f0));
        float hi1 = __bfloat162float(__float2bfloat16(f1));
        size_t o = ((((size_t)bh * HD + d) * SS + s0) >> 1) + sp;
        ((u32*)vthi)[o] = pkbf(hi0, hi1);
        ((u32*)vtlo)[o] = pkbf(f0 - hi0, f1 - hi1);
    }
}

// ---------------------------------------------------------------------------
// Flash attention, bf16 HMMA 6-product (R7 math) + cp.async double buffering.
// Dynamic smem: 2 buffers x 4 arrays x (64*PADR) u32 = 73728 bytes.
// ---------------------------------------------------------------------------
#define PADR 36
#define ARR_U32 (64 * PADR)            // 2304 u32 = 9216 B per array
#define BUF_U32 (4 * ARR_U32)          // 9216 u32 per buffer
#define ATT_SMEM (2 * BUF_U32 * 4)     // 73728 bytes

__global__ __launch_bounds__(256) void attn_mma(
    const __nv_bfloat16* __restrict__ qhi_, const __nv_bfloat16* __restrict__ qlo_,
    const __nv_bfloat16* __restrict__ khi_, const __nv_bfloat16* __restrict__ klo_,
    const __nv_bfloat16* __restrict__ vthi_, const __nv_bfloat16* __restrict__ vtlo_,
    float* __restrict__ out) {
    extern __shared__ __align__(16) u32 dsm[];

    const int tid = threadIdx.x;
    const int w = tid >> 5, lane = tid & 31;
    const int g = lane >> 2, t = lane & 3;
    const int bh = blockIdx.y, b = bh >> 3, h = bh & 7;
    const int q0 = blockIdx.x * 128 + w * 16;

    const u32* qhi32 = (const u32*)qhi_;
    const u32* qlo32 = (const u32*)qlo_;
    const u32* khi32 = (const u32*)khi_;
    const u32* klo32 = (const u32*)klo_;
    const u32* vthi32 = (const u32*)vthi_;
    const u32* vtlo32 = (const u32*)vtlo_;

    const u32 sb = smem_u32p(dsm);
    const size_t kgbase = (size_t)(b * SS) * 256 + h * 32;
    const size_t vgbase = (size_t)bh * 64 * 2048;

    // per-thread load coordinates (2 chunks)
    const int s0c = tid >> 3,            c0c = tid & 7;
    const int s1c = (tid + 256) >> 3,    c1c = tid & 7;   // (tid+256)&7 == tid&7
    const u32 so0 = (u32)((s0c * PADR + c0c * 4) * 4);
    const u32 so1 = (u32)((s1c * PADR + c1c * 4) * 4);

    // ---- issue cp.async loads of tile kt into buffer buf ------------------
    auto issue = [&](int kt, int buf) {
        const u32 bb = sb + (u32)(buf * BUF_U32 * 4);
        const size_t kg = kgbase + (size_t)kt * 256;
        const size_t vg = vgbase + (kt >> 1);
        // chunk 0
        cpasync16(bb + so0,                   khi32  + kg + (size_t)s0c * 256 + c0c * 4);
        cpasync16(bb + so0 + ARR_U32 * 4,     klo32  + kg + (size_t)s0c * 256 + c0c * 4);
        cpasync16(bb + so0 + ARR_U32 * 8,     vthi32 + vg + (size_t)s0c * 2048 + c0c * 4);
        cpasync16(bb + so0 + ARR_U32 * 12,    vtlo32 + vg + (size_t)s0c * 2048 + c0c * 4);
        // chunk 1
        cpasync16(bb + so1,                   khi32  + kg + (size_t)s1c * 256 + c1c * 4);
        cpasync16(bb + so1 + ARR_U32 * 4,     klo32  + kg + (size_t)s1c * 256 + c1c * 4);
        cpasync16(bb + so1 + ARR_U32 * 8,     vthi32 + vg + (size_t)s1c * 2048 + c1c * 4);
        cpasync16(bb + so1 + ARR_U32 * 12,    vtlo32 + vg + (size_t)s1c * 2048 + c1c * 4);
        cp_commit();
    };

    // ---- Q fragments (R7 layout) ------------------------------------------
    u32 aQh[4][4], aQl[4][4];
    {
        const size_t rg  = (size_t)(b * SS + q0 + g) * 256 + h * 32;
        const size_t rg8 = rg + 8 * 256;
#pragma unroll
        for (int kb = 0; kb < 4; kb++) {
            aQh[kb][0] = qhi32[rg  + kb * 8 + t];
            aQh[kb][1] = qhi32[rg8 + kb * 8 + t];
            aQh[kb][2] = qhi32[rg  + kb * 8 + 4 + t];
            aQh[kb][3] = qhi32[rg8 + kb * 8 + 4 + t];
            aQl[kb][0] = qlo32[rg  + kb * 8 + t];
            aQl[kb][1] = qlo32[rg8 + kb * 8 + t];
            aQl[kb][2] = qlo32[rg  + kb * 8 + 4 + t];
            aQl[kb][3] = qlo32[rg8 + kb * 8 + 4 + t];
        }
    }

    float oacc[8][4];
#pragma unroll
    for (int j = 0; j < 8; j++)
#pragma unroll
        for (int e = 0; e < 4; e++) oacc[j][e] = 0.0f;
    float lsum0 = 0.0f, lsum1 = 0.0f;

    issue(0, 0);            // prologue: prefetch tile 0

    const int NT = SS / 64; // 64 tiles
    for (int tn = 0; tn < NT; tn++) {
        const int cur = tn & 1;
        cp_wait0();
        __syncthreads();    // tile tn visible; all warps done with tile tn-1
        if (tn + 1 < NT) issue((tn + 1) * 64, cur ^ 1);

        const u32* ksh_hi = dsm + cur * BUF_U32;
        const u32* ksh_lo = ksh_hi + ARR_U32;
        const u32* vsh_hi = ksh_hi + 2 * ARR_U32;
        const u32* vsh_lo = ksh_hi + 3 * ARR_U32;

        float sacc[8][4];
#pragma unroll
        for (int j = 0; j < 8; j++)
#pragma unroll
            for (int e = 0; e < 4; e++) sacc[j][e] = 0.0f;

#pragma unroll
        for (int kb = 0; kb < 4; kb++) {
#pragma unroll
            for (int j = 0; j < 8; j++) {
                int base = (j * 8 + g) * PADR + kb * 8 + t;
                u32 bh0 = ksh_hi[base], bh1 = ksh_hi[base + 4];
                u32 bl0 = ksh_lo[base], bl1 = ksh_lo[base + 4];
                mma16816(sacc[j], aQh[kb], bh0, bh1);
                mma16816(sacc[j], aQh[kb], bl0, bl1);
                mma16816(sacc[j], aQl[kb], bh0, bh1);
            }
        }

        u32 aPh[4][4], aPl[4][4];
#pragma unroll
        for (int j = 0; j < 8; j++) {
            float p0 = __expf(sacc[j][0]);
            float p1 = __expf(sacc[j][1]);
            float p2 = __expf(sacc[j][2]);
            float p3 = __expf(sacc[j][3]);
            lsum0 += p0 + p1;
            lsum1 += p2 + p3;
            float f0 = __bfloat162float(__float2bfloat16(p0));
            float f1 = __bfloat162float(__float2bfloat16(p1));
            float f2 = __bfloat162float(__float2bfloat16(p2));
            float f3 = __bfloat162float(__float2bfloat16(p3));
            int kbp = j >> 1, r0 = (j & 1) * 2;
            aPh[kbp][r0]     = pkbf(f0, f1);
            aPh[kbp][r0 + 1] = pkbf(f2, f3);
            aPl[kbp][r0]     = pkbf(p0 - f0, p1 - f1);
            aPl[kbp][r0 + 1] = pkbf(p2 - f2, p3 - f3);
        }

#pragma unroll
        for (int kbp = 0; kbp < 4; kbp++) {
#pragma unroll
            for (int j = 0; j < 8; j++) {
                int base = (j * 8 + g) * PADR + kbp * 8 + t;
                u32 bh0 = vsh_hi[base], bh1 = vsh_hi[base + 4];
                u32 bl0 = vsh_lo[base], bl1 = vsh_lo[base + 4];
                mma16816(oacc[j], aPh[kbp], bh0, bh1);
                mma16816(oacc[j], aPh[kbp], bl0, bl1);
                mma16816(oacc[j], aPl[kbp], bh0, bh1);
            }
        }
    }

    lsum0 += __shfl_xor_sync(0xFFFFFFFFu, lsum0, 1);
    lsum0 += __shfl_xor_sync(0xFFFFFFFFu, lsum0, 2);
    lsum1 += __shfl_xor_sync(0xFFFFFFFFu, lsum1, 1);
    lsum1 += __shfl_xor_sync(0xFFFFFFFFu, lsum1, 2);
    float inv0 = 1.0f / lsum0, inv1 = 1.0f / lsum1;

    float* o0 = out + (size_t)(b * SS + q0 + g) * 512 + h * 64;
    float* o1 = o0 + 8 * 512;
#pragma unroll
    for (int j = 0; j < 8; j++) {
        *(float2*)(o0 + j * 8 + 2 * t) = make_float2(oacc[j][0] * inv0, oacc[j][1] * inv0);
        *(float2*)(o1 + j * 8 + 2 * t) = make_float2(oacc[j][2] * inv1, oacc[j][3] * inv1);
    }
}

// ---------------------------------------------------------------------------
extern "C" void kernel_launch(void* const* d_in, const int* in_sizes, int n_in,
                              void* d_out, int out_size) {
    const float* x  = (const float*)d_in[0];
    const float* Wq = (const float*)d_in[1];
    const float* Wk = (const float*)d_in[2];
    const float* Wv = (const float*)d_in[3];
    const float* Wo = (const float*)d_in[4];
    float* out = (float*)d_out;

    float *q, *k, *v, *att;
    __nv_bfloat16 *qhi, *qlo, *khi, *klo, *vthi, *vtlo;
    cudaGetSymbolAddress((void**)&q,    g_q);
    cudaGetSymbolAddress((void**)&k,    g_k);
    cudaGetSymbolAddress((void**)&v,    g_v);
    cudaGetSymbolAddress((void**)&att,  g_att);
    cudaGetSymbolAddress((void**)&qhi,  g_qhi);
    cudaGetSymbolAddress((void**)&qlo,  g_qlo);
    cudaGetSymbolAddress((void**)&khi,  g_khi);
    cudaGetSymbolAddress((void**)&klo,  g_klo);
    cudaGetSymbolAddress((void**)&vthi, g_vthi);
    cudaGetSymbolAddress((void**)&vtlo, g_vtlo);

    // Unconditional (no static guard). Host-side persistent attribute.
    cudaFuncSetAttribute(attn_mma, cudaFuncAttributeMaxDynamicSharedMemorySize, ATT_SMEM);

    dim3 ggrid(512 / 128, MROWS / 128);   // (4, 64)

    gemm_nt<<<ggrid, 256>>>(x, Wq, q);
    gemm_nt<<<ggrid, 256>>>(x, Wk, k);
    gemm_nt<<<ggrid, 256>>>(x, Wv, v);

    int nch = MROWS * HH * 16;
    rope_split<<<(nch + 255) / 256, 256>>>(q, k, qhi, qlo, khi, klo);

    v_split_t<<<dim3(SS / 64, BB * HH), 256>>>(v, vthi, vtlo);

    attn_mma<<<dim3(SS / 128, BB * HH), 256, ATT_SMEM>>>(qhi, qlo, khi, klo, vthi, vtlo, att);

    gemm_nt<<<ggrid, 256>>>(att, Wo, out);
}

// round 16
// speedup vs baseline: 1.3709x; 1.0434x over previous
#include <cuda_runtime.h>
#include <cuda_bf16.h>
#include <math.h>
#include <stdint.h>

#define BB 2
#define SS 4096
#define DD 512
#define HH 8
#define HD 64
#define MROWS (BB*SS)   // 8192

typedef unsigned long long u64;
typedef unsigned int u32;

// ------------------------- device scratch ----------------------------------
__device__ float g_q[MROWS * DD];
__device__ float g_k[MROWS * DD];
__device__ float g_v[MROWS * DD];
__device__ float g_att[MROWS * DD];
__device__ __nv_bfloat16 g_qhi[MROWS * DD];
__device__ __nv_bfloat16 g_qlo[MROWS * DD];
__device__ __nv_bfloat16 g_khi[MROWS * DD];
__device__ __nv_bfloat16 g_klo[MROWS * DD];
__device__ __nv_bfloat16 g_vthi[MROWS * DD];   // layout [bh][d][s]
__device__ __nv_bfloat16 g_vtlo[MROWS * DD];

// ---------------- helpers ---------------------------------------------------
__device__ __forceinline__ u64 ffma2(u64 a, u64 b, u64 c) {
    u64 d; asm("fma.rn.f32x2 %0, %1, %2, %3;" : "=l"(d) : "l"(a), "l"(b), "l"(c)); return d;
}
__device__ __forceinline__ u64 pack2(float lo, float hi) {
    u64 r; asm("mov.b64 %0, {%1, %2};" : "=l"(r) : "f"(lo), "f"(hi)); return r;
}
__device__ __forceinline__ void lds_v2b64(u64 &a, u64 &b, unsigned addr) {
    asm volatile("ld.shared.v2.b64 {%0, %1}, [%2];" : "=l"(a), "=l"(b) : "r"(addr));
}
__device__ __forceinline__ u32 pkbf(float a, float b) {
    __nv_bfloat162 t = __floats2bfloat162_rn(a, b);
    return *(u32*)&t;
}
__device__ __forceinline__ u32 smem_u32p(const void* ptr) {
    u32 a;
    asm("{ .reg .u64 t; cvta.to.shared.u64 t, %1; cvt.u32.u64 %0, t; }" : "=r"(a) : "l"(ptr));
    return a;
}
__device__ __forceinline__ void cpasync16(u32 saddr, const void* g) {
    asm volatile("cp.async.cg.shared.global [%0], [%1], 16;" :: "r"(saddr), "l"(g) : "memory");
}
__device__ __forceinline__ void cp_commit() {
    asm volatile("cp.async.commit_group;" ::: "memory");
}
__device__ __forceinline__ void cp_wait0() {
    asm volatile("cp.async.wait_group 0;" ::: "memory");
}
__device__ __forceinline__ void ldmx4(u32 &r0, u32 &r1, u32 &r2, u32 &r3, u32 saddr) {
    asm volatile("ldmatrix.sync.aligned.m8n8.x4.shared.b16 {%0,%1,%2,%3}, [%4];"
                 : "=r"(r0), "=r"(r1), "=r"(r2), "=r"(r3) : "r"(saddr));
}

// ---------------- mma.sync bf16 (baseline PTX, works on sm_103) -------------
__device__ __forceinline__ void mma16816(float* c, const u32* a, u32 b0, u32 b1) {
    asm("mma.sync.aligned.m16n8k16.row.col.f32.bf16.bf16.f32 "
        "{%0,%1,%2,%3}, {%4,%5,%6,%7}, {%8,%9}, {%0,%1,%2,%3};"
        : "+f"(c[0]), "+f"(c[1]), "+f"(c[2]), "+f"(c[3])
        : "r"(a[0]), "r"(a[1]), "r"(a[2]), "r"(a[3]), "r"(b0), "r"(b1));
}

// ---------------------------------------------------------------------------
// C[M x 512] = A[M x 512] * W[512 x 512]^T  (FFMA2 SIMT gemm — R7 proven)
// ---------------------------------------------------------------------------
__global__ __launch_bounds__(256) void gemm_nt(const float* __restrict__ A,
                                               const float* __restrict__ W,
                                               float* __restrict__ C) {
    __shared__ float As[16][132];
    __shared__ float Ws[16][132];

    const int bm = blockIdx.y * 128;
    const int bn = blockIdx.x * 128;
    const int t  = threadIdx.x;
    const int tm = (t >> 4) * 8;
    const int tn = (t & 15) * 8;

    u64 acc2[8][4];
#pragma unroll
    for (int i = 0; i < 8; i++)
#pragma unroll
        for (int j = 0; j < 4; j++) acc2[i][j] = 0ull;

    const unsigned sW = (unsigned)__cvta_generic_to_shared(&Ws[0][0]);

    for (int k0 = 0; k0 < 512; k0 += 16) {
#pragma unroll
        for (int i = 0; i < 2; i++) {
            int idx = t + i * 256;
            int row = idx >> 2;
            int kc  = (idx & 3) << 2;
            float4 av = *(const float4*)(A + (size_t)(bm + row) * 512 + k0 + kc);
            As[kc + 0][row] = av.x; As[kc + 1][row] = av.y;
            As[kc + 2][row] = av.z; As[kc + 3][row] = av.w;
            float4 wv = *(const float4*)(W + (size_t)(bn + row) * 512 + k0 + kc);
            Ws[kc + 0][row] = wv.x; Ws[kc + 1][row] = wv.y;
            Ws[kc + 2][row] = wv.z; Ws[kc + 3][row] = wv.w;
        }
        __syncthreads();

#pragma unroll
        for (int k = 0; k < 16; k++) {
            float4 a0 = *(const float4*)&As[k][tm];
            float4 a1 = *(const float4*)&As[k][tm + 4];
            u64 b2[4];
            unsigned wb = sW + (unsigned)(k * 132 + tn) * 4u;
            lds_v2b64(b2[0], b2[1], wb);
            lds_v2b64(b2[2], b2[3], wb + 16u);
            float a[8] = {a0.x, a0.y, a0.z, a0.w, a1.x, a1.y, a1.z, a1.w};
#pragma unroll
            for (int i = 0; i < 8; i++) {
                u64 ai = pack2(a[i], a[i]);
#pragma unroll
                for (int j = 0; j < 4; j++)
                    acc2[i][j] = ffma2(ai, b2[j], acc2[i][j]);
            }
        }
        __syncthreads();
    }

#pragma unroll
    for (int i = 0; i < 8; i++) {
        union { u64 u[2]; float4 f; } o0, o1;
        o0.u[0] = acc2[i][0]; o0.u[1] = acc2[i][1];
        o1.u[0] = acc2[i][2]; o1.u[1] = acc2[i][3];
        float* crow = C + (size_t)(bm + tm + i) * 512 + bn + tn;
        *(float4*)crow       = o0.f;
        *(float4*)(crow + 4) = o1.f;
    }
}

// ---------------------------------------------------------------------------
// Fused axial RoPE + bf16 split (R9-proven): q scaled by 0.125.
// ---------------------------------------------------------------------------
__global__ __launch_bounds__(256) void rope_split(const float* __restrict__ q,
                                                  const float* __restrict__ k,
                                                  __nv_bfloat16* __restrict__ qhi,
                                                  __nv_bfloat16* __restrict__ qlo,
                                                  __nv_bfloat16* __restrict__ khi,
                                                  __nv_bfloat16* __restrict__ klo) {
    int idx = blockIdx.x * 256 + threadIdx.x;
    if (idx >= MROWS * HH * 16) return;
    int c   = idx & 15;
    int rh  = idx >> 4;
    int h   = rh & 7;
    int row = rh >> 3;
    int s   = row & (SS - 1);

    int d0 = c * 4;
    float pos; int jb;
    if (d0 < 32) { pos = (float)(s >> 5); jb = c * 2; }
    else         { pos = (float)(s & 31); jb = (c - 8) * 2; }

    const float L = 13.2877123795494f / 16.0f;
    float a0 = pos * exp2f(-(float)jb * L);
    float a1 = pos * exp2f(-(float)(jb + 1) * L);
    float s0, c0, s1, c1;
    sincosf(a0, &s0, &c0);
    sincosf(a1, &s1, &c1);

    size_t base = (size_t)row * 512 + h * 64 + d0;
    int ui = (int)(base >> 2);

    {
        float4 x = *(const float4*)(q + base);
        float f[4];
        f[0] = (x.x * c0 - x.y * s0) * 0.125f;
        f[1] = (x.x * s0 + x.y * c0) * 0.125f;
        f[2] = (x.z * c1 - x.w * s1) * 0.125f;
        f[3] = (x.z * s1 + x.w * c1) * 0.125f;
        float hh[4];
#pragma unroll
        for (int e = 0; e < 4; e++) hh[e] = __bfloat162float(__float2bfloat16(f[e]));
        ((uint2*)qhi)[ui] = make_uint2(pkbf(hh[0], hh[1]), pkbf(hh[2], hh[3]));
        ((uint2*)qlo)[ui] = make_uint2(pkbf(f[0] - hh[0], f[1] - hh[1]),
                                       pkbf(f[2] - hh[2], f[3] - hh[3]));
    }
    {
        float4 x = *(const float4*)(k + base);
        float f[4];
        f[0] = x.x * c0 - x.y * s0;
        f[1] = x.x * s0 + x.y * c0;
        f[2] = x.z * c1 - x.w * s1;
        f[3] = x.z * s1 + x.w * c1;
        float hh[4];
#pragma unroll
        for (int e = 0; e < 4; e++) hh[e] = __bfloat162float(__float2bfloat16(f[e]));
        ((uint2*)khi)[ui] = make_uint2(pkbf(hh[0], hh[1]), pkbf(hh[2], hh[3]));
        ((uint2*)klo)[ui] = make_uint2(pkbf(f[0] - hh[0], f[1] - hh[1]),
                                       pkbf(f[2] - hh[2], f[3] - hh[3]));
    }
}

// ---------------------------------------------------------------------------
// Transpose + split V: v[b,s,h,d] -> vt[bh][d][s] in bf16 hi/lo (R9-proven).
// ---------------------------------------------------------------------------
__global__ __launch_bounds__(256) void v_split_t(const float* __restrict__ v,
                                                 __nv_bfloat16* __restrict__ vthi,
                                                 __nv_bfloat16* __restrict__ vtlo) {
    __shared__ float tile[64][65];
    const int bh = blockIdx.y;
    const int b  = bh >> 3;
    const int h  = bh & 7;
    const int s0 = blockIdx.x * 64;
    const int t  = threadIdx.x;

#pragma unroll
    for (int i = 0; i < 16; i++) {
        int idx = t + i * 256;
        int sl = idx >> 6, d = idx & 63;
        tile[sl][d] = v[((size_t)(b * SS) + s0 + sl) * DD + h * HD + d];
    }
    __syncthreads();

#pragma unroll
    for (int i = 0; i < 8; i++) {
        int j = t + i * 256;
        int d = j >> 5, sp = j & 31;
        float f0 = tile[sp * 2][d], f1 = tile[sp * 2 + 1][d];
        float hi0 = __bfloat162float(__float2bfloat16(f0));
        float hi1 = __bfloat162float(__float2bfloat16(f1));
        size_t o = ((((size_t)bh * HD + d) * SS + s0) >> 1) + sp;
        ((u32*)vthi)[o] = pkbf(hi0, hi1);
        ((u32*)vtlo)[o] = pkbf(f0 - hi0, f1 - hi1);
    }
}

// ---------------------------------------------------------------------------
// Flash attention, bf16 HMMA 6-product + cp.async double buffering + ldmatrix.
// Per (j,kb) one ldmatrix.x4 fetches {bh0,bh1,bl0,bl1} (hi matrix pair + lo
// matrix pair) — 64 ldmatrix per warp per tile vs 256 scalar LDS before.
// All ldmatrix addresses verified 16B-aligned (144·lr + 16·sel + 9216·s + ...).
// ---------------------------------------------------------------------------
#define PADR 36
#define ARR_U32 (64 * PADR)            // 2304 u32 = 9216 B per array
#define BUF_U32 (4 * ARR_U32)          // per buffer: khi,klo,vhi,vlo
#define ATT_SMEM (2 * BUF_U32 * 4)     // 73728 bytes

__global__ __launch_bounds__(256) void attn_mma(
    const __nv_bfloat16* __restrict__ qhi_, const __nv_bfloat16* __restrict__ qlo_,
    const __nv_bfloat16* __restrict__ khi_, const __nv_bfloat16* __restrict__ klo_,
    const __nv_bfloat16* __restrict__ vthi_, const __nv_bfloat16* __restrict__ vtlo_,
    float* __restrict__ out) {
    extern __shared__ __align__(16) u32 dsm[];

    const int tid = threadIdx.x;
    const int w = tid >> 5, lane = tid & 31;
    const int g = lane >> 2, t = lane & 3;
    const int bh = blockIdx.y, b = bh >> 3, h = bh & 7;
    const int q0 = blockIdx.x * 128 + w * 16;

    const u32* qhi32 = (const u32*)qhi_;
    const u32* qlo32 = (const u32*)qlo_;
    const u32* khi32 = (const u32*)khi_;
    const u32* klo32 = (const u32*)klo_;
    const u32* vthi32 = (const u32*)vthi_;
    const u32* vtlo32 = (const u32*)vtlo_;

    const u32 sb = smem_u32p(dsm);
    const size_t kgbase = (size_t)(b * SS) * 256 + h * 32;
    const size_t vgbase = (size_t)bh * 64 * 2048;

    // per-thread cp.async coordinates (2 chunks)
    const int s0c = tid >> 3,         c0c = tid & 7;
    const int s1c = (tid + 256) >> 3, c1c = tid & 7;
    const u32 so0 = (u32)((s0c * PADR + c0c * 4) * 4);
    const u32 so1 = (u32)((s1c * PADR + c1c * 4) * 4);

    auto issue = [&](int kt, int buf) {
        const u32 bb = sb + (u32)(buf * BUF_U32 * 4);
        const size_t kg = kgbase + (size_t)kt * 256;
        const size_t vg = vgbase + (kt >> 1);
        cpasync16(bb + so0,                khi32  + kg + (size_t)s0c * 256 + c0c * 4);
        cpasync16(bb + so0 + ARR_U32 * 4,  klo32  + kg + (size_t)s0c * 256 + c0c * 4);
        cpasync16(bb + so0 + ARR_U32 * 8,  vthi32 + vg + (size_t)s0c * 2048 + c0c * 4);
        cpasync16(bb + so0 + ARR_U32 * 12, vtlo32 + vg + (size_t)s0c * 2048 + c0c * 4);
        cpasync16(bb + so1,                khi32  + kg + (size_t)s1c * 256 + c1c * 4);
        cpasync16(bb + so1 + ARR_U32 * 4,  klo32  + kg + (size_t)s1c * 256 + c1c * 4);
        cpasync16(bb + so1 + ARR_U32 * 8,  vthi32 + vg + (size_t)s1c * 2048 + c1c * 4);
        cpasync16(bb + so1 + ARR_U32 * 12, vtlo32 + vg + (size_t)s1c * 2048 + c1c * 4);
        cp_commit();
    };

    // ldmatrix per-lane byte offset within a (hi,lo) array pair:
    //  sel = lane>>3: 0 -> hi matrix0, 1 -> hi matrix1 (+16B),
    //                 2 -> lo matrix0, 3 -> lo matrix1 (+16B)
    const int sel = lane >> 3, lr = lane & 7;
    const u32 lmoff = (u32)(((lr * PADR) + (sel & 1) * 4 + (sel >> 1) * ARR_U32) * 4);

    // ---- Q fragments (R7 layout) ------------------------------------------
    u32 aQh[4][4], aQl[4][4];
    {
        const size_t rg  = (size_t)(b * SS + q0 + g) * 256 + h * 32;
        const size_t rg8 = rg + 8 * 256;
#pragma unroll
        for (int kb = 0; kb < 4; kb++) {
            aQh[kb][0] = qhi32[rg  + kb * 8 + t];
            aQh[kb][1] = qhi32[rg8 + kb * 8 + t];
            aQh[kb][2] = qhi32[rg  + kb * 8 + 4 + t];
            aQh[kb][3] = qhi32[rg8 + kb * 8 + 4 + t];
            aQl[kb][0] = qlo32[rg  + kb * 8 + t];
            aQl[kb][1] = qlo32[rg8 + kb * 8 + t];
            aQl[kb][2] = qlo32[rg  + kb * 8 + 4 + t];
            aQl[kb][3] = qlo32[rg8 + kb * 8 + 4 + t];
        }
    }

    float oacc[8][4];
#pragma unroll
    for (int j = 0; j < 8; j++)
#pragma unroll
        for (int e = 0; e < 4; e++) oacc[j][e] = 0.0f;
    float lsum0 = 0.0f, lsum1 = 0.0f;

    issue(0, 0);

    const int NT = SS / 64;
    for (int tn = 0; tn < NT; tn++) {
        const int cur = tn & 1;
        cp_wait0();
        __syncthreads();
        if (tn + 1 < NT) issue((tn + 1) * 64, cur ^ 1);

        const u32 kbuf = sb + (u32)(cur * BUF_U32 * 4) + lmoff;             // khi/klo pair
        const u32 vbuf = kbuf + (u32)(2 * ARR_U32 * 4);                     // vhi/vlo pair

        float sacc[8][4];
#pragma unroll
        for (int j = 0; j < 8; j++)
#pragma unroll
            for (int e = 0; e < 4; e++) sacc[j][e] = 0.0f;

#pragma unroll
        for (int kb = 0; kb < 4; kb++) {
#pragma unroll
            for (int j = 0; j < 8; j++) {
                u32 r0, r1, r2, r3;
                ldmx4(r0, r1, r2, r3, kbuf + (u32)((j * 8 * PADR + kb * 8) * 4));
                mma16816(sacc[j], aQh[kb], r0, r1);
                mma16816(sacc[j], aQh[kb], r2, r3);
                mma16816(sacc[j], aQl[kb], r0, r1);
            }
        }

        u32 aPh[4][4], aPl[4][4];
#pragma unroll
        for (int j = 0; j < 8; j++) {
            float p0 = __expf(sacc[j][0]);
            float p1 = __expf(sacc[j][1]);
            float p2 = __expf(sacc[j][2]);
            float p3 = __expf(sacc[j][3]);
            lsum0 += p0 + p1;
            lsum1 += p2 + p3;
            float f0 = __bfloat162float(__float2bfloat16(p0));
            float f1 = __bfloat162float(__float2bfloat16(p1));
            float f2 = __bfloat162float(__float2bfloat16(p2));
            float f3 = __bfloat162float(__float2bfloat16(p3));
            int kbp = j >> 1, r0 = (j & 1) * 2;
            aPh[kbp][r0]     = pkbf(f0, f1);
            aPh[kbp][r0 + 1] = pkbf(f2, f3);
            aPl[kbp][r0]     = pkbf(p0 - f0, p1 - f1);
            aPl[kbp][r0 + 1] = pkbf(p2 - f2, p3 - f3);
        }

#pragma unroll
        for (int kbp = 0; kbp < 4; kbp++) {
#pragma unroll
            for (int j = 0; j < 8; j++) {
                u32 r0, r1, r2, r3;
                ldmx4(r0, r1, r2, r3, vbuf + (u32)((j * 8 * PADR + kbp * 8) * 4));
                mma16816(oacc[j], aPh[kbp], r0, r1);
                mma16816(oacc[j], aPh[kbp], r2, r3);
                mma16816(oacc[j], aPl[kbp], r0, r1);
            }
        }
    }

    lsum0 += __shfl_xor_sync(0xFFFFFFFFu, lsum0, 1);
    lsum0 += __shfl_xor_sync(0xFFFFFFFFu, lsum0, 2);
    lsum1 += __shfl_xor_sync(0xFFFFFFFFu, lsum1, 1);
    lsum1 += __shfl_xor_sync(0xFFFFFFFFu, lsum1, 2);
    float inv0 = 1.0f / lsum0, inv1 = 1.0f / lsum1;

    float* o0 = out + (size_t)(b * SS + q0 + g) * 512 + h * 64;
    float* o1 = o0 + 8 * 512;
#pragma unroll
    for (int j = 0; j < 8; j++) {
        *(float2*)(o0 + j * 8 + 2 * t) = make_float2(oacc[j][0] * inv0, oacc[j][1] * inv0);
        *(float2*)(o1 + j * 8 + 2 * t) = make_float2(oacc[j][2] * inv1, oacc[j][3] * inv1);
    }
}

// ---------------------------------------------------------------------------
extern "C" void kernel_launch(void* const* d_in, const int* in_sizes, int n_in,
                              void* d_out, int out_size) {
    const float* x  = (const float*)d_in[0];
    const float* Wq = (const float*)d_in[1];
    const float* Wk = (const float*)d_in[2];
    const float* Wv = (const float*)d_in[3];
    const float* Wo = (const float*)d_in[4];
    float* out = (float*)d_out;

    float *q, *k, *v, *att;
    __nv_bfloat16 *qhi, *qlo, *khi, *klo, *vthi, *vtlo;
    cudaGetSymbolAddress((void**)&q,    g_q);
    cudaGetSymbolAddress((void**)&k,    g_k);
    cudaGetSymbolAddress((void**)&v,    g_v);
    cudaGetSymbolAddress((void**)&att,  g_att);
    cudaGetSymbolAddress((void**)&qhi,  g_qhi);
    cudaGetSymbolAddress((void**)&qlo,  g_qlo);
    cudaGetSymbolAddress((void**)&khi,  g_khi);
    cudaGetSymbolAddress((void**)&klo,  g_klo);
    cudaGetSymbolAddress((void**)&vthi, g_vthi);
    cudaGetSymbolAddress((void**)&vtlo, g_vtlo);

    cudaFuncSetAttribute(attn_mma, cudaFuncAttributeMaxDynamicSharedMemorySize, ATT_SMEM);

    dim3 ggrid(512 / 128, MROWS / 128);   // (4, 64)

    gemm_nt<<<ggrid, 256>>>(x, Wq, q);
    gemm_nt<<<ggrid, 256>>>(x, Wk, k);
    gemm_nt<<<ggrid, 256>>>(x, Wv, v);

    int nch = MROWS * HH * 16;
    rope_split<<<(nch + 255) / 256, 256>>>(q, k, qhi, qlo, khi, klo);

    v_split_t<<<dim3(SS / 64, BB * HH), 256>>>(v, vthi, vtlo);

    attn_mma<<<dim3(SS / 128, BB * HH), 256, ATT_SMEM>>>(qhi, qlo, khi, klo, vthi, vtlo, att);

    gemm_nt<<<ggrid, 256>>>(att, Wo, out);
}

// round 17
// speedup vs baseline: 1.6574x; 1.2090x over previous
#include <cuda_runtime.h>
#include <cuda_fp16.h>
#include <math.h>
#include <stdint.h>

#define BB 2
#define SS 4096
#define DD 512
#define HH 8
#define HD 64
#define MROWS (BB*SS)   // 8192

typedef unsigned long long u64;
typedef unsigned int u32;

// ------------------------- device scratch ----------------------------------
__device__ float g_q[MROWS * DD];
__device__ float g_k[MROWS * DD];
__device__ float g_v[MROWS * DD];
__device__ float g_att[MROWS * DD];
__device__ __half g_qh[MROWS * DD];    // fp16(q * 0.125), post-rope
__device__ __half g_kh[MROWS * DD];    // fp16 hi of k, post-rope
__device__ __half g_kl[MROWS * DD];    // fp16 lo of k
__device__ __half g_vth[MROWS * DD];   // V^T [bh][d][s] fp16 hi
__device__ __half g_vtl[MROWS * DD];   // V^T fp16 lo

// ---------------- helpers ---------------------------------------------------
__device__ __forceinline__ u64 ffma2(u64 a, u64 b, u64 c) {
    u64 d; asm("fma.rn.f32x2 %0, %1, %2, %3;" : "=l"(d) : "l"(a), "l"(b), "l"(c)); return d;
}
__device__ __forceinline__ u64 pack2(float lo, float hi) {
    u64 r; asm("mov.b64 %0, {%1, %2};" : "=l"(r) : "f"(lo), "f"(hi)); return r;
}
__device__ __forceinline__ void lds_v2b64(u64 &a, u64 &b, unsigned addr) {
    asm volatile("ld.shared.v2.b64 {%0, %1}, [%2];" : "=l"(a), "=l"(b) : "r"(addr));
}
__device__ __forceinline__ u32 pkh(float a, float b) {
    __half2 t = __floats2half2_rn(a, b);   // x=a (low), y=b (high)
    return *(u32*)&t;
}
__device__ __forceinline__ float h2f(float f) {       // fp16 round-trip
    return __half2float(__float2half_rn(f));
}
__device__ __forceinline__ u32 smem_u32p(const void* ptr) {
    u32 a;
    asm("{ .reg .u64 t; cvta.to.shared.u64 t, %1; cvt.u32.u64 %0, t; }" : "=r"(a) : "l"(ptr));
    return a;
}
__device__ __forceinline__ void cpasync16(u32 saddr, const void* g) {
    asm volatile("cp.async.cg.shared.global [%0], [%1], 16;" :: "r"(saddr), "l"(g) : "memory");
}
__device__ __forceinline__ void cp_commit() {
    asm volatile("cp.async.commit_group;" ::: "memory");
}
__device__ __forceinline__ void cp_wait0() {
    asm volatile("cp.async.wait_group 0;" ::: "memory");
}
__device__ __forceinline__ void ldmx4(u32 &r0, u32 &r1, u32 &r2, u32 &r3, u32 saddr) {
    asm volatile("ldmatrix.sync.aligned.m8n8.x4.shared.b16 {%0,%1,%2,%3}, [%4];"
                 : "=r"(r0), "=r"(r1), "=r"(r2), "=r"(r3) : "r"(saddr));
}

// ---------------- mma.sync fp16 (baseline PTX, works on sm_103) -------------
__device__ __forceinline__ void mma16816h(float* c, const u32* a, u32 b0, u32 b1) {
    asm("mma.sync.aligned.m16n8k16.row.col.f32.f16.f16.f32 "
        "{%0,%1,%2,%3}, {%4,%5,%6,%7}, {%8,%9}, {%0,%1,%2,%3};"
        : "+f"(c[0]), "+f"(c[1]), "+f"(c[2]), "+f"(c[3])
        : "r"(a[0]), "r"(a[1]), "r"(a[2]), "r"(a[3]), "r"(b0), "r"(b1));
}

// ---------------------------------------------------------------------------
// C[M x 512] = A[M x 512] * W[512 x 512]^T  (FFMA2 SIMT gemm — R7 proven)
// ---------------------------------------------------------------------------
__global__ __launch_bounds__(256) void gemm_nt(const float* __restrict__ A,
                                               const float* __restrict__ W,
                                               float* __restrict__ C) {
    __shared__ float As[16][132];
    __shared__ float Ws[16][132];

    const int bm = blockIdx.y * 128;
    const int bn = blockIdx.x * 128;
    const int t  = threadIdx.x;
    const int tm = (t >> 4) * 8;
    const int tn = (t & 15) * 8;

    u64 acc2[8][4];
#pragma unroll
    for (int i = 0; i < 8; i++)
#pragma unroll
        for (int j = 0; j < 4; j++) acc2[i][j] = 0ull;

    const unsigned sW = (unsigned)__cvta_generic_to_shared(&Ws[0][0]);

    for (int k0 = 0; k0 < 512; k0 += 16) {
#pragma unroll
        for (int i = 0; i < 2; i++) {
            int idx = t + i * 256;
            int row = idx >> 2;
            int kc  = (idx & 3) << 2;
            float4 av = *(const float4*)(A + (size_t)(bm + row) * 512 + k0 + kc);
            As[kc + 0][row] = av.x; As[kc + 1][row] = av.y;
            As[kc + 2][row] = av.z; As[kc + 3][row] = av.w;
            float4 wv = *(const float4*)(W + (size_t)(bn + row) * 512 + k0 + kc);
            Ws[kc + 0][row] = wv.x; Ws[kc + 1][row] = wv.y;
            Ws[kc + 2][row] = wv.z; Ws[kc + 3][row] = wv.w;
        }
        __syncthreads();

#pragma unroll
        for (int k = 0; k < 16; k++) {
            float4 a0 = *(const float4*)&As[k][tm];
            float4 a1 = *(const float4*)&As[k][tm + 4];
            u64 b2[4];
            unsigned wb = sW + (unsigned)(k * 132 + tn) * 4u;
            lds_v2b64(b2[0], b2[1], wb);
            lds_v2b64(b2[2], b2[3], wb + 16u);
            float a[8] = {a0.x, a0.y, a0.z, a0.w, a1.x, a1.y, a1.z, a1.w};
#pragma unroll
            for (int i = 0; i < 8; i++) {
                u64 ai = pack2(a[i], a[i]);
#pragma unroll
                for (int j = 0; j < 4; j++)
                    acc2[i][j] = ffma2(ai, b2[j], acc2[i][j]);
            }
        }
        __syncthreads();
    }

#pragma unroll
    for (int i = 0; i < 8; i++) {
        union { u64 u[2]; float4 f; } o0, o1;
        o0.u[0] = acc2[i][0]; o0.u[1] = acc2[i][1];
        o1.u[0] = acc2[i][2]; o1.u[1] = acc2[i][3];
        float* crow = C + (size_t)(bm + tm + i) * 512 + bn + tn;
        *(float4*)crow       = o0.f;
        *(float4*)(crow + 4) = o1.f;
    }
}

// ---------------------------------------------------------------------------
// Fused axial RoPE + fp16 convert (R10-proven): q -> single fp16 (x0.125);
// k -> fp16 hi/lo split.
// ---------------------------------------------------------------------------
__global__ __launch_bounds__(256) void rope_h(const float* __restrict__ q,
                                              const float* __restrict__ k,
                                              __half* __restrict__ qh,
                                              __half* __restrict__ kh,
                                              __half* __restrict__ kl) {
    int idx = blockIdx.x * 256 + threadIdx.x;
    if (idx >= MROWS * HH * 16) return;
    int c   = idx & 15;
    int rh  = idx >> 4;
    int h   = rh & 7;
    int row = rh >> 3;
    int s   = row & (SS - 1);

    int d0 = c * 4;
    float pos; int jb;
    if (d0 < 32) { pos = (float)(s >> 5); jb = c * 2; }
    else         { pos = (float)(s & 31); jb = (c - 8) * 2; }

    const float L = 13.2877123795494f / 16.0f;
    float a0 = pos * exp2f(-(float)jb * L);
    float a1 = pos * exp2f(-(float)(jb + 1) * L);
    float s0, c0, s1, c1;
    sincosf(a0, &s0, &c0);
    sincosf(a1, &s1, &c1);

    size_t base = (size_t)row * 512 + h * 64 + d0;
    int ui = (int)(base >> 2);

    {
        float4 x = *(const float4*)(q + base);
        float e0 = (x.x * c0 - x.y * s0) * 0.125f;
        float o0 = (x.x * s0 + x.y * c0) * 0.125f;
        float e1 = (x.z * c1 - x.w * s1) * 0.125f;
        float o1 = (x.z * s1 + x.w * c1) * 0.125f;
        ((uint2*)qh)[ui] = make_uint2(pkh(e0, o0), pkh(e1, o1));
    }
    {
        float4 x = *(const float4*)(k + base);
        float f[4];
        f[0] = x.x * c0 - x.y * s0;
        f[1] = x.x * s0 + x.y * c0;
        f[2] = x.z * c1 - x.w * s1;
        f[3] = x.z * s1 + x.w * c1;
        float hh[4];
#pragma unroll
        for (int e = 0; e < 4; e++) hh[e] = h2f(f[e]);
        ((uint2*)kh)[ui] = make_uint2(pkh(hh[0], hh[1]), pkh(hh[2], hh[3]));
        ((uint2*)kl)[ui] = make_uint2(pkh(f[0] - hh[0], f[1] - hh[1]),
                                      pkh(f[2] - hh[2], f[3] - hh[3]));
    }
}

// ---------------------------------------------------------------------------
// Transpose + fp16 split V (R10-proven): v[b,s,h,d] -> vt[bh][d][s].
// ---------------------------------------------------------------------------
__global__ __launch_bounds__(256) void v_split_t(const float* __restrict__ v,
                                                 __half* __restrict__ vth,
                                                 __half* __restrict__ vtl) {
    __shared__ float tile[64][65];
    const int bh = blockIdx.y;
    const int b  = bh >> 3;
    const int h  = bh & 7;
    const int s0 = blockIdx.x * 64;
    const int t  = threadIdx.x;

#pragma unroll
    for (int i = 0; i < 16; i++) {
        int idx = t + i * 256;
        int sl = idx >> 6, d = idx & 63;
        tile[sl][d] = v[((size_t)(b * SS) + s0 + sl) * DD + h * HD + d];
    }
    __syncthreads();

#pragma unroll
    for (int i = 0; i < 8; i++) {
        int j = t + i * 256;
        int d = j >> 5, sp = j & 31;
        float f0 = tile[sp * 2][d], f1 = tile[sp * 2 + 1][d];
        float hi0 = h2f(f0), hi1 = h2f(f1);
        size_t o = ((((size_t)bh * HD + d) * SS + s0) >> 1) + sp;
        ((u32*)vth)[o] = pkh(hi0, hi1);
        ((u32*)vtl)[o] = pkh(f0 - hi0, f1 - hi1);
    }
}

// ---------------------------------------------------------------------------
// Flash attention: fp16 HMMA 4-product (R10 math) + ldmatrix (R16) +
// cp.async double buffering (R12) + __launch_bounds__(256,2) for 2 CTAs/SM.
// p' = exp2(s*log2e - 8): exact power-of-2 scale cancels in O = sum p'v / sum p'.
// ---------------------------------------------------------------------------
#define PADR 36
#define ARR_U32 (64 * PADR)            // 2304 u32 = 9216 B per array
#define BUF_U32 (4 * ARR_U32)          // per buffer: kh,kl,vh,vl
#define ATT_SMEM (2 * BUF_U32 * 4)     // 73728 bytes; x2 CTAs = 147456 <= 228K

__global__ __launch_bounds__(256, 2) void attn_mma(
    const __half* __restrict__ qh_, const __half* __restrict__ kh_,
    const __half* __restrict__ kl_,
    const __half* __restrict__ vth_, const __half* __restrict__ vtl_,
    float* __restrict__ out) {
    extern __shared__ __align__(16) u32 dsm[];

    const int tid = threadIdx.x;
    const int w = tid >> 5, lane = tid & 31;
    const int g = lane >> 2, t = lane & 3;
    const int bh = blockIdx.y, b = bh >> 3, h = bh & 7;
    const int q0 = blockIdx.x * 128 + w * 16;

    const u32* qh32 = (const u32*)qh_;
    const u32* kh32 = (const u32*)kh_;
    const u32* kl32 = (const u32*)kl_;
    const u32* vth32 = (const u32*)vth_;
    const u32* vtl32 = (const u32*)vtl_;

    const u32 sb = smem_u32p(dsm);
    const size_t kgbase = (size_t)(b * SS) * 256 + h * 32;
    const size_t vgbase = (size_t)bh * 64 * 2048;

    // per-thread cp.async coordinates (2 chunks)
    const int s0c = tid >> 3,         c0c = tid & 7;
    const int s1c = (tid + 256) >> 3, c1c = tid & 7;
    const u32 so0 = (u32)((s0c * PADR + c0c * 4) * 4);
    const u32 so1 = (u32)((s1c * PADR + c1c * 4) * 4);

    auto issue = [&](int kt, int buf) {
        const u32 bb = sb + (u32)(buf * BUF_U32 * 4);
        const size_t kg = kgbase + (size_t)kt * 256;
        const size_t vg = vgbase + (kt >> 1);
        cpasync16(bb + so0,                kh32  + kg + (size_t)s0c * 256 + c0c * 4);
        cpasync16(bb + so0 + ARR_U32 * 4,  kl32  + kg + (size_t)s0c * 256 + c0c * 4);
        cpasync16(bb + so0 + ARR_U32 * 8,  vth32 + vg + (size_t)s0c * 2048 + c0c * 4);
        cpasync16(bb + so0 + ARR_U32 * 12, vtl32 + vg + (size_t)s0c * 2048 + c0c * 4);
        cpasync16(bb + so1,                kh32  + kg + (size_t)s1c * 256 + c1c * 4);
        cpasync16(bb + so1 + ARR_U32 * 4,  kl32  + kg + (size_t)s1c * 256 + c1c * 4);
        cpasync16(bb + so1 + ARR_U32 * 8,  vth32 + vg + (size_t)s1c * 2048 + c1c * 4);
        cpasync16(bb + so1 + ARR_U32 * 12, vtl32 + vg + (size_t)s1c * 2048 + c1c * 4);
        cp_commit();
    };

    // ldmatrix per-lane offset: sel 0/1 -> hi matrix0/1, sel 2/3 -> lo matrix0/1
    const int sel = lane >> 3, lr = lane & 7;
    const u32 lmoff = (u32)(((lr * PADR) + (sel & 1) * 4 + (sel >> 1) * ARR_U32) * 4);

    // ---- Q fragments (single fp16) ----------------------------------------
    u32 aQ[4][4];
    {
        const size_t rg  = (size_t)(b * SS + q0 + g) * 256 + h * 32;
        const size_t rg8 = rg + 8 * 256;
#pragma unroll
        for (int kb = 0; kb < 4; kb++) {
            aQ[kb][0] = qh32[rg  + kb * 8 + t];
            aQ[kb][1] = qh32[rg8 + kb * 8 + t];
            aQ[kb][2] = qh32[rg  + kb * 8 + 4 + t];
            aQ[kb][3] = qh32[rg8 + kb * 8 + 4 + t];
        }
    }

    float oacc[8][4];
#pragma unroll
    for (int j = 0; j < 8; j++)
#pragma unroll
        for (int e = 0; e < 4; e++) oacc[j][e] = 0.0f;
    float lsum0 = 0.0f, lsum1 = 0.0f;

    issue(0, 0);

    const int NT = SS / 64;
    for (int tn = 0; tn < NT; tn++) {
        const int cur = tn & 1;
        cp_wait0();
        __syncthreads();
        if (tn + 1 < NT) issue((tn + 1) * 64, cur ^ 1);

        const u32 kbuf = sb + (u32)(cur * BUF_U32 * 4) + lmoff;   // kh/kl pair
        const u32 vbuf = kbuf + (u32)(2 * ARR_U32 * 4);           // vh/vl pair

        float sacc[8][4];
#pragma unroll
        for (int j = 0; j < 8; j++)
#pragma unroll
            for (int e = 0; e < 4; e++) sacc[j][e] = 0.0f;

#pragma unroll
        for (int kb = 0; kb < 4; kb++) {
#pragma unroll
            for (int j = 0; j < 8; j++) {
                u32 r0, r1, r2, r3;
                ldmx4(r0, r1, r2, r3, kbuf + (u32)((j * 8 * PADR + kb * 8) * 4));
                mma16816h(sacc[j], aQ[kb], r0, r1);    // Q * Khi
                mma16816h(sacc[j], aQ[kb], r2, r3);    // Q * Klo
            }
        }

        // p' = exp2(s*log2e - 8); single fp16 P
        const float L2E = 1.44269504f;
        u32 aP[4][4];
#pragma unroll
        for (int j = 0; j < 8; j++) {
            float p0 = exp2f(sacc[j][0] * L2E - 8.0f);
            float p1 = exp2f(sacc[j][1] * L2E - 8.0f);
            float p2 = exp2f(sacc[j][2] * L2E - 8.0f);
            float p3 = exp2f(sacc[j][3] * L2E - 8.0f);
            lsum0 += p0 + p1;
            lsum1 += p2 + p3;
            int kbp = j >> 1, r0 = (j & 1) * 2;
            aP[kbp][r0]     = pkh(p0, p1);
            aP[kbp][r0 + 1] = pkh(p2, p3);
        }

#pragma unroll
        for (int kbp = 0; kbp < 4; kbp++) {
#pragma unroll
            for (int j = 0; j < 8; j++) {
                u32 r0, r1, r2, r3;
                ldmx4(r0, r1, r2, r3, vbuf + (u32)((j * 8 * PADR + kbp * 8) * 4));
                mma16816h(oacc[j], aP[kbp], r0, r1);   // P * Vhi
                mma16816h(oacc[j], aP[kbp], r2, r3);   // P * Vlo
            }
        }
    }

    lsum0 += __shfl_xor_sync(0xFFFFFFFFu, lsum0, 1);
    lsum0 += __shfl_xor_sync(0xFFFFFFFFu, lsum0, 2);
    lsum1 += __shfl_xor_sync(0xFFFFFFFFu, lsum1, 1);
    lsum1 += __shfl_xor_sync(0xFFFFFFFFu, lsum1, 2);
    float inv0 = 1.0f / lsum0, inv1 = 1.0f / lsum1;

    float* o0 = out + (size_t)(b * SS + q0 + g) * 512 + h * 64;
    float* o1 = o0 + 8 * 512;
#pragma unroll
    for (int j = 0; j < 8; j++) {
        *(float2*)(o0 + j * 8 + 2 * t) = make_float2(oacc[j][0] * inv0, oacc[j][1] * inv0);
        *(float2*)(o1 + j * 8 + 2 * t) = make_float2(oacc[j][2] * inv1, oacc[j][3] * inv1);
    }
}

// ---------------------------------------------------------------------------
extern "C" void kernel_launch(void* const* d_in, const int* in_sizes, int n_in,
                              void* d_out, int out_size) {
    const float* x  = (const float*)d_in[0];
    const float* Wq = (const float*)d_in[1];
    const float* Wk = (const float*)d_in[2];
    const float* Wv = (const float*)d_in[3];
    const float* Wo = (const float*)d_in[4];
    float* out = (float*)d_out;

    float *q, *k, *v, *att;
    __half *qh, *kh, *kl, *vth, *vtl;
    cudaGetSymbolAddress((void**)&q,   g_q);
    cudaGetSymbolAddress((void**)&k,   g_k);
    cudaGetSymbolAddress((void**)&v,   g_v);
    cudaGetSymbolAddress((void**)&att, g_att);
    cudaGetSymbolAddress((void**)&qh,  g_qh);
    cudaGetSymbolAddress((void**)&kh,  g_kh);
    cudaGetSymbolAddress((void**)&kl,  g_kl);
    cudaGetSymbolAddress((void**)&vth, g_vth);
    cudaGetSymbolAddress((void**)&vtl, g_vtl);

    cudaFuncSetAttribute(attn_mma, cudaFuncAttributeMaxDynamicSharedMemorySize, ATT_SMEM);

    dim3 ggrid(512 / 128, MROWS / 128);   // (4, 64)

    gemm_nt<<<ggrid, 256>>>(x, Wq, q);
    gemm_nt<<<ggrid, 256>>>(x, Wk, k);
    gemm_nt<<<ggrid, 256>>>(x, Wv, v);

    int nch = MROWS * HH * 16;
    rope_h<<<(nch + 255) / 256, 256>>>(q, k, qh, kh, kl);

    v_split_t<<<dim3(SS / 64, BB * HH), 256>>>(v, vth, vtl);

    attn_mma<<<dim3(SS / 128, BB * HH), 256, ATT_SMEM>>>(qh, kh, kl, vth, vtl, att);

    gemm_nt<<<ggrid, 256>>>(att, Wo, out);
}